// round 2
// baseline (speedup 1.0000x reference)
#include <cuda_runtime.h>
#include <cstdint>

// OctreeConvBnRelu: out = ReLU(BN(einsum('nkc,kco->no', gather(data, neigh), W)))
// N=300000, K=27, Cin=32, Cout=64.
//
// Round 2: fix neigh dtype (harness delivers int32, not int64 — JAX x64 off).
//  - conv kernel: 64 nodes x 64 outs per block, 256 threads, 4x4 register tile
//    per thread using packed fma.rn.f32x2 (2 MACs/lane/inst on sm_103a).
//  - BN stats fused: block-reduce channel sums + atomicAdd into __device__ arrays.
//  - finalize kernel computes scale/shift; elementwise kernel applies BN+ReLU.
//  - All state re-initialized every launch (graph-replay safe, no allocations).

#define DEVFN __device__ __forceinline__

DEVFN unsigned long long pack2(float lo, float hi) {
    unsigned long long r;
    asm("mov.b64 %0, {%1, %2};" : "=l"(r) : "f"(lo), "f"(hi));
    return r;
}
DEVFN void unpack2(unsigned long long v, float& lo, float& hi) {
    asm("mov.b64 {%0, %1}, %2;" : "=f"(lo), "=f"(hi) : "l"(v));
}
DEVFN unsigned long long fma2(unsigned long long a, unsigned long long b,
                              unsigned long long c) {
    unsigned long long d;
    asm("fma.rn.f32x2 %0, %1, %2, %3;" : "=l"(d) : "l"(a), "l"(b), "l"(c));
    return d;
}

// BN statistics / affine params (device globals: no allocations allowed)
__device__ float g_sum[64];
__device__ float g_sumsq[64];
__device__ __align__(16) float g_scale[64];
__device__ __align__(16) float g_shift[64];

__global__ void zero_stats_kernel() {
    int t = threadIdx.x;
    if (t < 64) { g_sum[t] = 0.0f; g_sumsq[t] = 0.0f; }
}

// ---------------------------------------------------------------------------
// Conv kernel: tile = 64 nodes x 64 outputs, 256 threads.
// Thread (tn = tid&15, to = tid>>4) owns nodes [4tn..4tn+3] x outs [4to..4to+3].
// ---------------------------------------------------------------------------
__global__ __launch_bounds__(256) void conv_kernel(
    const float* __restrict__ data,          // [N, 32]
    const int* __restrict__ neigh,           // [N, 27]  (int32!)
    const float* __restrict__ weight,        // [27, 32, 64]
    float* __restrict__ out,                 // [N, 64] raw conv result
    int N)
{
    __shared__ int   idx_all[27 * 64];                 // neighbor idx per (k, node)
    __shared__ float g_s[32 * 68];                     // gathered, c-major [c][node], pad 68
    __shared__ unsigned long long w2_s[32 * 64];       // W[k] duplicated into f32x2 pairs
    __shared__ float red[2 * 16 * 64];                 // BN partial reduction

    const int tid = threadIdx.x;
    const int tn = tid & 15;
    const int to = tid >> 4;
    const int n0 = blockIdx.x * 64;
    const int nb = tn * 4;
    const int ob = to * 4;

    // Load all 27 neighbor indices for the 64 nodes of this tile.
    for (int e = tid; e < 27 * 64; e += 256) {
        int r = e / 27;
        int k = e - r * 27;
        int n = n0 + r;
        int v = (n < N) ? neigh[(size_t)n * 27 + k] : -1;
        if (v >= N) v = -1;              // defensive: never read out of bounds
        idx_all[k * 64 + r] = v;
    }

    unsigned long long acc[2][4];   // [node-pair][out], f32x2 packed
    #pragma unroll
    for (int p = 0; p < 2; p++)
        #pragma unroll
        for (int j = 0; j < 4; j++) acc[p][j] = 0ull;

    for (int k = 0; k < 27; k++) {
        __syncthreads();   // previous iteration's readers of g_s/w2_s are done

        // Fill W[k] slice, duplicating each weight into both f32x2 halves.
        const float* wk = weight + k * 2048;
        #pragma unroll
        for (int j = 0; j < 8; j++) {
            int e = tid + j * 256;          // 0..2047 = c*64 + o
            float v = wk[e];
            w2_s[e] = pack2(v, v);
        }

        // Gather 64 rows x 32 floats, stored transposed (c-major).
        #pragma unroll
        for (int j = 0; j < 2; j++) {
            int e = tid + j * 256;          // 0..511 float4 chunks
            int r = e >> 3;                  // node 0..63
            int q = e & 7;                   // float4 column group 0..7
            int idx = idx_all[k * 64 + r];
            float4 v = make_float4(0.f, 0.f, 0.f, 0.f);
            if (idx >= 0)
                v = *(const float4*)(data + (size_t)idx * 32 + q * 4);
            g_s[(q * 4 + 0) * 68 + r] = v.x;
            g_s[(q * 4 + 1) * 68 + r] = v.y;
            g_s[(q * 4 + 2) * 68 + r] = v.z;
            g_s[(q * 4 + 3) * 68 + r] = v.w;
        }
        __syncthreads();

        // 64x64x32 sub-GEMM, 4x4 per-thread tile with packed f32x2 FMA.
        #pragma unroll
        for (int c = 0; c < 32; c++) {
            ulonglong2 g01 = *(const ulonglong2*)(g_s + c * 68 + nb);      // nodes (0,1),(2,3)
            ulonglong2 wab = *(const ulonglong2*)(w2_s + c * 64 + ob);     // outs j0,j1 (dup)
            ulonglong2 wcd = *(const ulonglong2*)(w2_s + c * 64 + ob + 2); // outs j2,j3 (dup)
            acc[0][0] = fma2(g01.x, wab.x, acc[0][0]);
            acc[0][1] = fma2(g01.x, wab.y, acc[0][1]);
            acc[0][2] = fma2(g01.x, wcd.x, acc[0][2]);
            acc[0][3] = fma2(g01.x, wcd.y, acc[0][3]);
            acc[1][0] = fma2(g01.y, wab.x, acc[1][0]);
            acc[1][1] = fma2(g01.y, wab.y, acc[1][1]);
            acc[1][2] = fma2(g01.y, wcd.x, acc[1][2]);
            acc[1][3] = fma2(g01.y, wcd.y, acc[1][3]);
        }
    }

    // Unpack accumulators: a[i][j], node i = nb+i, out = ob+j.
    float a[4][4];
    #pragma unroll
    for (int j = 0; j < 4; j++) {
        unpack2(acc[0][j], a[0][j], a[1][j]);
        unpack2(acc[1][j], a[2][j], a[3][j]);
    }

    // Store raw conv output (float4 per node).
    #pragma unroll
    for (int i = 0; i < 4; i++) {
        int n = n0 + nb + i;
        if (n < N) {
            float4 v = make_float4(a[i][0], a[i][1], a[i][2], a[i][3]);
            *(float4*)(out + (size_t)n * 64 + ob) = v;
        }
    }

    // BN partial sums (valid nodes only): per-thread over its 4 nodes.
    float s1[4] = {0.f, 0.f, 0.f, 0.f};
    float s2[4] = {0.f, 0.f, 0.f, 0.f};
    #pragma unroll
    for (int i = 0; i < 4; i++) {
        if (n0 + nb + i < N) {
            #pragma unroll
            for (int j = 0; j < 4; j++) {
                float v = a[i][j];
                s1[j] += v;
                s2[j] += v * v;
            }
        }
    }
    __syncthreads();   // done with g_s/w2_s; red buffer is exclusive anyway
    #pragma unroll
    for (int j = 0; j < 4; j++) {
        red[tn * 64 + ob + j]        = s1[j];
        red[1024 + tn * 64 + ob + j] = s2[j];
    }
    __syncthreads();
    if (tid < 64) {
        float t1 = 0.f, t2 = 0.f;
        #pragma unroll
        for (int r = 0; r < 16; r++) {
            t1 += red[r * 64 + tid];
            t2 += red[1024 + r * 64 + tid];
        }
        atomicAdd(&g_sum[tid], t1);
        atomicAdd(&g_sumsq[tid], t2);
    }
}

// ---------------------------------------------------------------------------
__global__ void finalize_stats_kernel(const float* __restrict__ gamma,
                                      const float* __restrict__ beta,
                                      float invN)
{
    int c = threadIdx.x;
    if (c < 64) {
        float mean = g_sum[c] * invN;
        float var  = fmaxf(g_sumsq[c] * invN - mean * mean, 0.0f);
        float sc   = gamma[c] * rsqrtf(var + 1e-5f);
        g_scale[c] = sc;
        g_shift[c] = beta[c] - mean * sc;
    }
}

__global__ __launch_bounds__(256) void bn_relu_kernel(float* __restrict__ out,
                                                      int total4)
{
    int i = blockIdx.x * 256 + threadIdx.x;
    if (i < total4) {
        float4 x = ((const float4*)out)[i];
        int cq = i & 15;   // 64 channels / 4 per float4
        float4 sc = ((const float4*)g_scale)[cq];
        float4 sh = ((const float4*)g_shift)[cq];
        float4 y;
        y.x = fmaxf(fmaf(x.x, sc.x, sh.x), 0.0f);
        y.y = fmaxf(fmaf(x.y, sc.y, sh.y), 0.0f);
        y.z = fmaxf(fmaf(x.z, sc.z, sh.z), 0.0f);
        y.w = fmaxf(fmaf(x.w, sc.w, sh.w), 0.0f);
        ((float4*)out)[i] = y;
    }
}

// ---------------------------------------------------------------------------
extern "C" void kernel_launch(void* const* d_in, const int* in_sizes, int n_in,
                              void* d_out, int out_size)
{
    const float* data   = (const float*)d_in[0];   // [N,32] f32
    const int*   neigh  = (const int*)d_in[1];     // [N,27] int32 (JAX x64 off)
    const float* weight = (const float*)d_in[2];   // [27,32,64] f32
    const float* gamma  = (const float*)d_in[3];   // [64] f32
    const float* beta   = (const float*)d_in[4];   // [64] f32
    float* out = (float*)d_out;                    // [N,64] f32

    int N = in_sizes[0] / 32;

    zero_stats_kernel<<<1, 64>>>();
    conv_kernel<<<(N + 63) / 64, 256>>>(data, neigh, weight, out, N);
    finalize_stats_kernel<<<1, 64>>>(gamma, beta, 1.0f / (float)N);
    int total4 = N * 16;   // N*64/4 float4 elements
    bn_relu_kernel<<<(total4 + 255) / 256, 256>>>(out, total4);
}

// round 5
// speedup vs baseline: 2.2854x; 2.2854x over previous
#include <cuda_runtime.h>
#include <cuda_bf16.h>
#include <cstdint>

// OctreeConvBnRelu via warp-level mma.sync (HMMA bf16) — tcgen05 unavailable
// because the harness targets plain sm_103 (no 'a' suffix).
// conv block = 128 nodes x 64 outs, 256 thr (8 warps, one m16 tile each).
// fp32 emulated as bf16 hi/lo split, 3 products (hi*hi + hi*lo + lo*hi).
// Weights pre-split into mma B-fragment order once per launch.

#define DEVFN __device__ __forceinline__
#define SW128(b) ((b) ^ (((b) >> 3) & 0x70))

DEVFN uint32_t smem_u32(const void* p) {
    uint32_t a;
    asm("{ .reg .u64 t; cvta.to.shared.u64 t, %1; cvt.u32.u64 %0, t; }" : "=r"(a) : "l"(p));
    return a;
}
DEVFN uint32_t pack_bf16(float x, float y) {
    __nv_bfloat162 v(__float2bfloat16(x), __float2bfloat16(y));  // x = low half
    return *(uint32_t*)&v;
}
DEVFN float bf16_res(float x) { return x - __bfloat162float(__float2bfloat16(x)); }

DEVFN void ldmatrix_x4(uint32_t* r, uint32_t addr) {
    asm volatile("ldmatrix.sync.aligned.m8n8.x4.shared.b16 {%0,%1,%2,%3}, [%4];"
                 : "=r"(r[0]), "=r"(r[1]), "=r"(r[2]), "=r"(r[3]) : "r"(addr));
}
DEVFN void mma_bf16(float* d, const uint32_t* a, uint32_t b0, uint32_t b1) {
    asm volatile(
        "mma.sync.aligned.m16n8k16.row.col.f32.bf16.bf16.f32 "
        "{%0,%1,%2,%3}, {%4,%5,%6,%7}, {%8,%9}, {%0,%1,%2,%3};"
        : "+f"(d[0]), "+f"(d[1]), "+f"(d[2]), "+f"(d[3])
        : "r"(a[0]), "r"(a[1]), "r"(a[2]), "r"(a[3]), "r"(b0), "r"(b1));
}

// ------------------------- globals -------------------------
__device__ float g_sum[64];
__device__ float g_sumsq[64];
__device__ __align__(16) float g_scale[64];
__device__ __align__(16) float g_shift[64];
// B fragments: [27][ntile 8][kstep 4][lane 32] x uint2  (8 KB per k-offset)
__device__ __align__(16) uint2 g_Bfrag[27 * 1024];

__global__ void zero_stats_kernel() {
    int t = threadIdx.x;
    if (t < 64) { g_sum[t] = 0.0f; g_sumsq[t] = 0.0f; }
}

// ------------------------- weight prep -------------------------
// mma m16n8k16 B fragment (k x n): lane l holds B[2q + {0,1}][g] (reg0) and
// B[2q+8 + {0,1}][g] (reg1), q = l&3, g = l>>2.  ksteps: 0,1 = hi(c 0:16,16:32),
// 2,3 = lo(c 0:16,16:32).
__global__ __launch_bounds__(256) void prep_weights_kernel(const float* __restrict__ weight) {
    int k = blockIdx.x;
    int lane = threadIdx.x & 31;
    int nt = threadIdx.x >> 5;            // warp = ntile 0..7
    int q = lane & 3;
    int g = lane >> 2;
    int n = nt * 8 + g;
    const float* wk = weight + k * 2048;  // [32 c][64 o]

    #pragma unroll
    for (int ks = 0; ks < 4; ks++) {
        int cb = (ks & 1) * 16 + 2 * q;
        float w0 = wk[cb * 64 + n];
        float w1 = wk[(cb + 1) * 64 + n];
        float w8 = wk[(cb + 8) * 64 + n];
        float w9 = wk[(cb + 9) * 64 + n];
        uint2 v;
        if (ks < 2) {
            v.x = pack_bf16(w0, w1);
            v.y = pack_bf16(w8, w9);
        } else {
            v.x = pack_bf16(bf16_res(w0), bf16_res(w1));
            v.y = pack_bf16(bf16_res(w8), bf16_res(w9));
        }
        g_Bfrag[((k * 8 + nt) * 4 + ks) * 32 + lane] = v;
    }
}

// ------------------------- conv kernel -------------------------
__global__ __launch_bounds__(256) void conv_kernel(
    const float* __restrict__ data,     // [N,32]
    const int* __restrict__ neigh,      // [N,27] int32
    float* __restrict__ out,            // [N,64]
    int N)
{
    __shared__ __align__(1024) uint8_t sA[128 * 128];  // rows: [hi 64B | lo 64B], SW128
    __shared__ __align__(16) uint2 sB[1024];           // B frags for current k
    __shared__ int s_idx[27 * 128];
    __shared__ float red_sum[8 * 64];
    __shared__ float red_sq[8 * 64];

    const int tid = threadIdx.x;
    const int w = tid >> 5;
    const int lane = tid & 31;
    const int n0 = blockIdx.x * 128;

    // preload neighbor indices (coalesced)
    {
        const int* base = neigh + (size_t)n0 * 27;
        for (int e = tid; e < 27 * 128; e += 256) {
            int r = e / 27;
            int kk = e - r * 27;
            int v = (n0 + r < N) ? base[e] : -1;
            if ((unsigned)v >= (unsigned)N) v = -1;
            s_idx[kk * 128 + r] = v;
        }
    }

    const uint32_t aA = smem_u32(sA);
    // gather mapping: chunk j (0..7), row = p*32 + (tid>>3)
    const int j = tid & 7;
    const int rbase = tid >> 3;
    const bool isHi = (j < 4);
    const int fg = (j & 3) * 8;                       // source channel group
    const uint32_t chunk_byte = isHi ? (j * 16) : (64 + (j - 4) * 16);

    // ldmatrix addresses (const per thread): ks 0..3 -> bytes 0,32,64,96
    uint32_t lm_addr[4];
    {
        int row = w * 16 + (lane & 15);
        int half = (lane >> 4) * 16;
        #pragma unroll
        for (int ks = 0; ks < 4; ks++)
            lm_addr[ks] = aA + SW128((uint32_t)(row * 128 + ks * 32 + half));
    }

    float acc[8][4];
    #pragma unroll
    for (int nt = 0; nt < 8; nt++)
        #pragma unroll
        for (int i = 0; i < 4; i++) acc[nt][i] = 0.0f;

    __syncthreads();

    for (int k = 0; k < 27; k++) {
        // ---- stage B fragments (8 KB, coalesced) ----
        {
            const uint4* src = (const uint4*)(g_Bfrag + (size_t)k * 1024);
            uint4* dst = (uint4*)sB;
            dst[tid] = src[tid];
            dst[tid + 256] = src[tid + 256];
        }
        // ---- gather A: 128 rows x 32 f32 -> bf16 hi/lo, SW128 ----
        const int* idxk = s_idx + k * 128;
        #pragma unroll
        for (int p = 0; p < 4; p++) {
            int r = p * 32 + rbase;
            int idx = idxk[r];
            float4 va = make_float4(0.f, 0.f, 0.f, 0.f);
            float4 vb = va;
            if (idx >= 0) {
                const float4* dp = (const float4*)(data + (size_t)idx * 32 + fg);
                va = dp[0]; vb = dp[1];
            }
            float f[8] = {va.x, va.y, va.z, va.w, vb.x, vb.y, vb.z, vb.w};
            uint32_t u[4];
            if (isHi) {
                #pragma unroll
                for (int i = 0; i < 4; i++) u[i] = pack_bf16(f[2 * i], f[2 * i + 1]);
            } else {
                #pragma unroll
                for (int i = 0; i < 4; i++)
                    u[i] = pack_bf16(bf16_res(f[2 * i]), bf16_res(f[2 * i + 1]));
            }
            uint32_t st = aA + SW128((uint32_t)(r * 128 + chunk_byte));
            asm volatile("st.shared.v4.b32 [%0], {%1,%2,%3,%4};"
                         :: "r"(st), "r"(u[0]), "r"(u[1]), "r"(u[2]), "r"(u[3]) : "memory");
        }
        __syncthreads();

        // ---- compute: A frags via ldmatrix, B frags via LDS, 6 HMMA per ntile ----
        uint32_t af[4][4];
        #pragma unroll
        for (int ks = 0; ks < 4; ks++) ldmatrix_x4(af[ks], lm_addr[ks]);

        #pragma unroll
        for (int nt = 0; nt < 8; nt++) {
            const uint2* bp = sB + nt * 128 + lane;
            uint2 b0 = bp[0];        // hi, c 0:16
            uint2 b1 = bp[32];       // hi, c 16:32
            uint2 b2 = bp[64];       // lo, c 0:16
            uint2 b3 = bp[96];       // lo, c 16:32
            mma_bf16(acc[nt], af[0], b0.x, b0.y);   // hi*hi
            mma_bf16(acc[nt], af[1], b1.x, b1.y);
            mma_bf16(acc[nt], af[0], b2.x, b2.y);   // hi*lo
            mma_bf16(acc[nt], af[1], b3.x, b3.y);
            mma_bf16(acc[nt], af[2], b0.x, b0.y);   // lo*hi
            mma_bf16(acc[nt], af[3], b1.x, b1.y);
        }
        __syncthreads();   // consumers done before next-iter smem overwrite
    }

    // ---- epilogue ----
    // C fragment: lane: rows m0+g, m0+g+8; cols nt*8 + 2q, +1  (q=lane&3, g=lane>>2)
    const int q = lane & 3;
    const int g = lane >> 2;
    const int row0 = n0 + w * 16 + g;
    const int row1 = row0 + 8;

    if (row0 < N) {
        float* po = out + (size_t)row0 * 64 + 2 * q;
        #pragma unroll
        for (int nt = 0; nt < 8; nt++)
            *(float2*)(po + nt * 8) = make_float2(acc[nt][0], acc[nt][1]);
    }
    if (row1 < N) {
        float* po = out + (size_t)row1 * 64 + 2 * q;
        #pragma unroll
        for (int nt = 0; nt < 8; nt++)
            *(float2*)(po + nt * 8) = make_float2(acc[nt][2], acc[nt][3]);
    }

    // BN partials: invalid rows accumulated exact zeros (A rows zeroed), safe to sum.
    float ps[16], pq[16];
    #pragma unroll
    for (int nt = 0; nt < 8; nt++) {
        ps[2 * nt]     = acc[nt][0] + acc[nt][2];
        ps[2 * nt + 1] = acc[nt][1] + acc[nt][3];
        pq[2 * nt]     = acc[nt][0] * acc[nt][0] + acc[nt][2] * acc[nt][2];
        pq[2 * nt + 1] = acc[nt][1] * acc[nt][1] + acc[nt][3] * acc[nt][3];
    }
    #pragma unroll
    for (int i = 0; i < 16; i++) {
        #pragma unroll
        for (int off = 4; off < 32; off <<= 1) {
            ps[i] += __shfl_xor_sync(0xffffffffu, ps[i], off);
            pq[i] += __shfl_xor_sync(0xffffffffu, pq[i], off);
        }
    }
    if (g == 0) {   // lanes 0..3 hold warp totals
        #pragma unroll
        for (int nt = 0; nt < 8; nt++) {
            int c = nt * 8 + 2 * q;
            red_sum[w * 64 + c]     = ps[2 * nt];
            red_sum[w * 64 + c + 1] = ps[2 * nt + 1];
            red_sq[w * 64 + c]      = pq[2 * nt];
            red_sq[w * 64 + c + 1]  = pq[2 * nt + 1];
        }
    }
    __syncthreads();
    if (tid < 64) {
        float t = 0.f;
        #pragma unroll
        for (int ww = 0; ww < 8; ww++) t += red_sum[ww * 64 + tid];
        atomicAdd(&g_sum[tid], t);
    } else if (tid < 128) {
        int c = tid - 64;
        float t = 0.f;
        #pragma unroll
        for (int ww = 0; ww < 8; ww++) t += red_sq[ww * 64 + c];
        atomicAdd(&g_sumsq[c], t);
    }
}

// ------------------------- BN tail -------------------------
__global__ void finalize_stats_kernel(const float* __restrict__ gamma,
                                      const float* __restrict__ beta,
                                      float invN)
{
    int c = threadIdx.x;
    if (c < 64) {
        float mean = g_sum[c] * invN;
        float var  = fmaxf(g_sumsq[c] * invN - mean * mean, 0.0f);
        float sc   = gamma[c] * rsqrtf(var + 1e-5f);
        g_scale[c] = sc;
        g_shift[c] = beta[c] - mean * sc;
    }
}

__global__ __launch_bounds__(256) void bn_relu_kernel(float* __restrict__ out, int total4) {
    int i = blockIdx.x * 256 + threadIdx.x;
    if (i < total4) {
        float4 x = ((const float4*)out)[i];
        int cq = i & 15;
        float4 sc = ((const float4*)g_scale)[cq];
        float4 sh = ((const float4*)g_shift)[cq];
        float4 y;
        y.x = fmaxf(fmaf(x.x, sc.x, sh.x), 0.0f);
        y.y = fmaxf(fmaf(x.y, sc.y, sh.y), 0.0f);
        y.z = fmaxf(fmaf(x.z, sc.z, sh.z), 0.0f);
        y.w = fmaxf(fmaf(x.w, sc.w, sh.w), 0.0f);
        ((float4*)out)[i] = y;
    }
}

// ------------------------- launch -------------------------
extern "C" void kernel_launch(void* const* d_in, const int* in_sizes, int n_in,
                              void* d_out, int out_size)
{
    const float* data   = (const float*)d_in[0];   // [N,32]
    const int*   neigh  = (const int*)d_in[1];     // [N,27] int32
    const float* weight = (const float*)d_in[2];   // [27,32,64]
    const float* gamma  = (const float*)d_in[3];
    const float* beta   = (const float*)d_in[4];
    float* out = (float*)d_out;

    int N = in_sizes[0] / 32;

    zero_stats_kernel<<<1, 64>>>();
    prep_weights_kernel<<<27, 256>>>(weight);
    conv_kernel<<<(N + 127) / 128, 256>>>(data, neigh, out, N);
    finalize_stats_kernel<<<1, 64>>>(gamma, beta, 1.0f / (float)N);
    int total4 = N * 16;
    bn_relu_kernel<<<(total4 + 255) / 256, 256>>>(out, total4);
}

// round 7
// speedup vs baseline: 3.5549x; 1.5555x over previous
#include <cuda_runtime.h>
#include <cuda_bf16.h>
#include <cstdint>

// OctreeConvBnRelu via warp-level mma.sync (HMMA bf16), cp.async pipelined.
// Round 6:
//  - data pre-split once per launch into g_dataHL rows [hi bf16 32ch | lo bf16 32ch]
//    (128B/row) so the k-loop gather is a pure cp.async byte copy (swizzled).
//  - 2-stage double-buffered A/B tiles, cp.async.commit/wait pipeline.
//  - conv block = 128 nodes x 64 outs, 256 thr, bf16 hi/lo 3-product (6 HMMA).

#define DEVFN __device__ __forceinline__
#define SW128(b) ((b) ^ (((b) >> 3) & 0x70))

DEVFN uint32_t smem_u32(const void* p) {
    uint32_t a;
    asm("{ .reg .u64 t; cvta.to.shared.u64 t, %1; cvt.u32.u64 %0, t; }" : "=r"(a) : "l"(p));
    return a;
}
DEVFN uint32_t pack_bf16(float x, float y) {
    __nv_bfloat162 v(__float2bfloat16(x), __float2bfloat16(y));  // x = low half
    return *(uint32_t*)&v;
}
DEVFN float bf16_res(float x) { return x - __bfloat162float(__float2bfloat16(x)); }

DEVFN void ldmatrix_x4(uint32_t* r, uint32_t addr) {
    asm volatile("ldmatrix.sync.aligned.m8n8.x4.shared.b16 {%0,%1,%2,%3}, [%4];"
                 : "=r"(r[0]), "=r"(r[1]), "=r"(r[2]), "=r"(r[3]) : "r"(addr));
}
DEVFN void mma_bf16(float* d, const uint32_t* a, uint32_t b0, uint32_t b1) {
    asm volatile(
        "mma.sync.aligned.m16n8k16.row.col.f32.bf16.bf16.f32 "
        "{%0,%1,%2,%3}, {%4,%5,%6,%7}, {%8,%9}, {%0,%1,%2,%3};"
        : "+f"(d[0]), "+f"(d[1]), "+f"(d[2]), "+f"(d[3])
        : "r"(a[0]), "r"(a[1]), "r"(a[2]), "r"(a[3]), "r"(b0), "r"(b1));
}
DEVFN void cp_async16(uint32_t smem_dst, const void* gsrc) {
    asm volatile("cp.async.cg.shared.global [%0], [%1], 16;"
                 :: "r"(smem_dst), "l"(gsrc) : "memory");
}
#define CP_COMMIT() asm volatile("cp.async.commit_group;" ::: "memory")

// ------------------------- globals -------------------------
__device__ float g_sum[64];
__device__ float g_sumsq[64];
__device__ __align__(16) float g_scale[64];
__device__ __align__(16) float g_shift[64];
// B fragments: [27][ntile 8][kstep 4][lane 32] x uint2  (8 KB per k-offset)
__device__ __align__(16) uint2 g_Bfrag[27 * 1024];
// pre-split data image: per row 128B = [hi bf16 ch0:32 | lo bf16 ch0:32]
static const int ROW_CAP = 301056;
__device__ __align__(16) uint8_t g_dataHL[(size_t)ROW_CAP * 128];
__device__ __align__(16) uint8_t g_zero_row[128];   // stays zero

__global__ void zero_stats_kernel() {
    int t = threadIdx.x;
    if (t < 64) { g_sum[t] = 0.0f; g_sumsq[t] = 0.0f; }
}

// ------------------------- data prep -------------------------
// one thread per half-row (16 channels): read 4 float4, emit 32B hi + 32B lo.
__global__ __launch_bounds__(256) void prep_data_kernel(const float* __restrict__ data, int N) {
    int t = blockIdx.x * 256 + threadIdx.x;
    int r = t >> 1, h = t & 1;
    if (r >= N || r >= ROW_CAP) return;
    const float4* src = (const float4*)(data + (size_t)r * 32 + h * 16);
    float f[16];
    #pragma unroll
    for (int i = 0; i < 4; i++) {
        float4 v = src[i];
        f[4 * i] = v.x; f[4 * i + 1] = v.y; f[4 * i + 2] = v.z; f[4 * i + 3] = v.w;
    }
    uint32_t hi[8], lo[8];
    #pragma unroll
    for (int i = 0; i < 8; i++) {
        hi[i] = pack_bf16(f[2 * i], f[2 * i + 1]);
        lo[i] = pack_bf16(bf16_res(f[2 * i]), bf16_res(f[2 * i + 1]));
    }
    uint4* dhi = (uint4*)(g_dataHL + (size_t)r * 128 + h * 32);
    uint4* dlo = (uint4*)(g_dataHL + (size_t)r * 128 + 64 + h * 32);
    dhi[0] = make_uint4(hi[0], hi[1], hi[2], hi[3]);
    dhi[1] = make_uint4(hi[4], hi[5], hi[6], hi[7]);
    dlo[0] = make_uint4(lo[0], lo[1], lo[2], lo[3]);
    dlo[1] = make_uint4(lo[4], lo[5], lo[6], lo[7]);
}

// ------------------------- weight prep -------------------------
// mma m16n8k16 B fragment: lane l holds B[2q+{0,1}][g] (reg0), B[2q+8+{0,1}][g]
// (reg1), q=l&3, g=l>>2. ksteps: 0,1 = hi(c0:16,c16:32); 2,3 = lo.
__global__ __launch_bounds__(256) void prep_weights_kernel(const float* __restrict__ weight) {
    int k = blockIdx.x;
    int lane = threadIdx.x & 31;
    int nt = threadIdx.x >> 5;
    int q = lane & 3;
    int g = lane >> 2;
    int n = nt * 8 + g;
    const float* wk = weight + k * 2048;  // [32 c][64 o]

    #pragma unroll
    for (int ks = 0; ks < 4; ks++) {
        int cb = (ks & 1) * 16 + 2 * q;
        float w0 = wk[cb * 64 + n];
        float w1 = wk[(cb + 1) * 64 + n];
        float w8 = wk[(cb + 8) * 64 + n];
        float w9 = wk[(cb + 9) * 64 + n];
        uint2 v;
        if (ks < 2) {
            v.x = pack_bf16(w0, w1);
            v.y = pack_bf16(w8, w9);
        } else {
            v.x = pack_bf16(bf16_res(w0), bf16_res(w1));
            v.y = pack_bf16(bf16_res(w8), bf16_res(w9));
        }
        g_Bfrag[((k * 8 + nt) * 4 + ks) * 32 + lane] = v;
    }
}

// ------------------------- conv kernel -------------------------
// dynamic smem: sA 2x16KB | sB 2x8KB  (total 48KB)
__global__ __launch_bounds__(256) void conv_kernel(
    const int* __restrict__ neigh,      // [N,27] int32
    float* __restrict__ out,            // [N,64]
    int N)
{
    extern __shared__ __align__(1024) uint8_t dyn[];
    uint8_t* sB = dyn + 32768;
    __shared__ int s_idx[27 * 128];
    __shared__ float red_sum[8 * 64];
    __shared__ float red_sq[8 * 64];

    const int tid = threadIdx.x;
    const int w = tid >> 5;
    const int lane = tid & 31;
    const int n0 = blockIdx.x * 128;

    const uint32_t aA = smem_u32(dyn);
    const uint32_t aB = aA + 32768;

    // preload neighbor indices (coalesced)
    {
        const int* base = neigh + (size_t)n0 * 27;
        for (int e = tid; e < 27 * 128; e += 256) {
            int r = e / 27;
            int kk = e - r * 27;
            int v = (n0 + r < N) ? base[e] : -1;
            if ((unsigned)v >= (unsigned)N) v = -1;
            s_idx[kk * 128 + r] = v;
        }
    }
    __syncthreads();

    // gather chunk mapping: per stage this thread copies 4 A-chunks + 2 B-chunks.
    const int jr = tid >> 3;        // row base (0..31), rows jr + 32*i
    const int jj = tid & 7;         // 16B chunk in row

    // ldmatrix relative offsets (within a stage's A buffer)
    uint32_t lm_rel[4];
    {
        int row = w * 16 + (lane & 15);
        int half = (lane >> 4) * 16;
        #pragma unroll
        for (int ks = 0; ks < 4; ks++)
            lm_rel[ks] = SW128((uint32_t)(row * 128 + ks * 32 + half));
    }

    float acc[8][4];
    #pragma unroll
    for (int nt = 0; nt < 8; nt++)
        #pragma unroll
        for (int i = 0; i < 4; i++) acc[nt][i] = 0.0f;

    // ---- pipeline stage issue ----
    auto issue_stage = [&](int k) {
        int sb = k & 1;
        // B frags: 8KB contiguous
        const uint8_t* bsrc = (const uint8_t*)g_Bfrag + (size_t)k * 8192 + tid * 16;
        uint32_t bdst = aB + sb * 8192 + tid * 16;
        cp_async16(bdst, bsrc);
        cp_async16(bdst + 4096, bsrc + 4096);
        // A gather: 4 chunks
        const int* idxk = s_idx + k * 128;
        #pragma unroll
        for (int i = 0; i < 4; i++) {
            int r = jr + i * 32;
            int idx = idxk[r];
            const uint8_t* src = (idx >= 0)
                ? g_dataHL + (size_t)idx * 128 + jj * 16
                : g_zero_row + jj * 16;
            uint32_t dst = aA + sb * 16384 + SW128((uint32_t)(r * 128 + jj * 16));
            cp_async16(dst, src);
        }
        CP_COMMIT();
    };

    issue_stage(0);

    for (int k = 0; k < 27; k++) {
        if (k + 1 < 27) {
            issue_stage(k + 1);
            asm volatile("cp.async.wait_group 1;" ::: "memory");
        } else {
            asm volatile("cp.async.wait_group 0;" ::: "memory");
        }
        __syncthreads();

        const uint32_t abase = aA + (k & 1) * 16384;
        uint32_t af[4][4];
        #pragma unroll
        for (int ks = 0; ks < 4; ks++) ldmatrix_x4(af[ks], abase + lm_rel[ks]);

        const uint2* bbuf = (const uint2*)(sB + (k & 1) * 8192);
        #pragma unroll
        for (int nt = 0; nt < 8; nt++) {
            const uint2* bp = bbuf + nt * 128 + lane;
            uint2 b0 = bp[0];        // hi, c 0:16
            uint2 b1 = bp[32];       // hi, c 16:32
            uint2 b2 = bp[64];       // lo, c 0:16
            uint2 b3 = bp[96];       // lo, c 16:32
            mma_bf16(acc[nt], af[0], b0.x, b0.y);   // hi*hi
            mma_bf16(acc[nt], af[1], b1.x, b1.y);
            mma_bf16(acc[nt], af[0], b2.x, b2.y);   // hi*lo
            mma_bf16(acc[nt], af[1], b3.x, b3.y);
            mma_bf16(acc[nt], af[2], b0.x, b0.y);   // lo*hi
            mma_bf16(acc[nt], af[3], b1.x, b1.y);
        }
        __syncthreads();   // readers done before buffer reuse
    }

    // ---- epilogue ----
    const int q = lane & 3;
    const int g = lane >> 2;
    const int row0 = n0 + w * 16 + g;
    const int row1 = row0 + 8;

    if (row0 < N) {
        float* po = out + (size_t)row0 * 64 + 2 * q;
        #pragma unroll
        for (int nt = 0; nt < 8; nt++)
            *(float2*)(po + nt * 8) = make_float2(acc[nt][0], acc[nt][1]);
    }
    if (row1 < N) {
        float* po = out + (size_t)row1 * 64 + 2 * q;
        #pragma unroll
        for (int nt = 0; nt < 8; nt++)
            *(float2*)(po + nt * 8) = make_float2(acc[nt][2], acc[nt][3]);
    }

    // BN partials (invalid rows contributed exact zeros)
    float ps[16], pq[16];
    #pragma unroll
    for (int nt = 0; nt < 8; nt++) {
        ps[2 * nt]     = acc[nt][0] + acc[nt][2];
        ps[2 * nt + 1] = acc[nt][1] + acc[nt][3];
        pq[2 * nt]     = acc[nt][0] * acc[nt][0] + acc[nt][2] * acc[nt][2];
        pq[2 * nt + 1] = acc[nt][1] * acc[nt][1] + acc[nt][3] * acc[nt][3];
    }
    #pragma unroll
    for (int i = 0; i < 16; i++) {
        #pragma unroll
        for (int off = 4; off < 32; off <<= 1) {
            ps[i] += __shfl_xor_sync(0xffffffffu, ps[i], off);
            pq[i] += __shfl_xor_sync(0xffffffffu, pq[i], off);
        }
    }
    if (g == 0) {
        #pragma unroll
        for (int nt = 0; nt < 8; nt++) {
            int c = nt * 8 + 2 * q;
            red_sum[w * 64 + c]     = ps[2 * nt];
            red_sum[w * 64 + c + 1] = ps[2 * nt + 1];
            red_sq[w * 64 + c]      = pq[2 * nt];
            red_sq[w * 64 + c + 1]  = pq[2 * nt + 1];
        }
    }
    __syncthreads();
    if (tid < 64) {
        float t = 0.f;
        #pragma unroll
        for (int ww = 0; ww < 8; ww++) t += red_sum[ww * 64 + tid];
        atomicAdd(&g_sum[tid], t);
    } else if (tid < 128) {
        int c = tid - 64;
        float t = 0.f;
        #pragma unroll
        for (int ww = 0; ww < 8; ww++) t += red_sq[ww * 64 + c];
        atomicAdd(&g_sumsq[c], t);
    }
}

// ------------------------- BN tail -------------------------
__global__ void finalize_stats_kernel(const float* __restrict__ gamma,
                                      const float* __restrict__ beta,
                                      float invN)
{
    int c = threadIdx.x;
    if (c < 64) {
        float mean = g_sum[c] * invN;
        float var  = fmaxf(g_sumsq[c] * invN - mean * mean, 0.0f);
        float sc   = gamma[c] * rsqrtf(var + 1e-5f);
        g_scale[c] = sc;
        g_shift[c] = beta[c] - mean * sc;
    }
}

__global__ __launch_bounds__(256) void bn_relu_kernel(float* __restrict__ out, int total4) {
    int i = blockIdx.x * 256 + threadIdx.x;
    if (i < total4) {
        float4 x = ((const float4*)out)[i];
        int cq = i & 15;
        float4 sc = ((const float4*)g_scale)[cq];
        float4 sh = ((const float4*)g_shift)[cq];
        float4 y;
        y.x = fmaxf(fmaf(x.x, sc.x, sh.x), 0.0f);
        y.y = fmaxf(fmaf(x.y, sc.y, sh.y), 0.0f);
        y.z = fmaxf(fmaf(x.z, sc.z, sh.z), 0.0f);
        y.w = fmaxf(fmaf(x.w, sc.w, sh.w), 0.0f);
        ((float4*)out)[i] = y;
    }
}

// ------------------------- launch -------------------------
extern "C" void kernel_launch(void* const* d_in, const int* in_sizes, int n_in,
                              void* d_out, int out_size)
{
    const float* data   = (const float*)d_in[0];   // [N,32]
    const int*   neigh  = (const int*)d_in[1];     // [N,27] int32
    const float* weight = (const float*)d_in[2];   // [27,32,64]
    const float* gamma  = (const float*)d_in[3];
    const float* beta   = (const float*)d_in[4];
    float* out = (float*)d_out;

    int N = in_sizes[0] / 32;

    static bool configured = false;
    if (!configured) {
        cudaFuncSetAttribute(conv_kernel,
                             cudaFuncAttributeMaxDynamicSharedMemorySize, 49152);
        configured = true;
    }

    zero_stats_kernel<<<1, 64>>>();
    prep_data_kernel<<<(2 * N + 255) / 256, 256>>>(data, N);
    prep_weights_kernel<<<27, 256>>>(weight);
    conv_kernel<<<(N + 127) / 128, 256, 49152>>>(neigh, out, N);
    finalize_stats_kernel<<<1, 64>>>(gamma, beta, 1.0f / (float)N);
    int total4 = N * 16;
    bn_relu_kernel<<<(total4 + 255) / 256, 256>>>(out, total4);
}

// round 9
// speedup vs baseline: 5.7234x; 1.6100x over previous
#include <cuda_runtime.h>
#include <cuda_fp16.h>
#include <cstdint>

// OctreeConvBnRelu via warp-level mma.sync (HMMA fp16, f32 accum).
// Round 9 (= R8 + the smem opt-in that R8 dropped):
//  - fp16 single-product (error ~2^-11*sqrt(2/3) ~ 5e-4 < 1e-3 gate).
//  - data pre-converted once to fp16 rows (64B) -> k-loop gather is cp.async copy.
//  - 3-stage cp.async pipeline, A 3x8KB + B 3x4KB = 36KB dynamic smem.
//  - static smem (s_idx + reductions) pushes total >48KB -> needs
//    cudaFuncSetAttribute opt-in (proven capture-safe in R7).
//  - bank-conflict-free 64B-row layout: chunk_phys = chunk ^ ((row>>1)&3).

#define DEVFN __device__ __forceinline__

DEVFN uint32_t smem_u32(const void* p) {
    uint32_t a;
    asm("{ .reg .u64 t; cvta.to.shared.u64 t, %1; cvt.u32.u64 %0, t; }" : "=r"(a) : "l"(p));
    return a;
}
DEVFN uint32_t pack_h2(float x, float y) {
    __half2 v = __halves2half2(__float2half_rn(x), __float2half_rn(y));  // x = low
    return *(uint32_t*)&v;
}
DEVFN void ldmatrix_x4(uint32_t* r, uint32_t addr) {
    asm volatile("ldmatrix.sync.aligned.m8n8.x4.shared.b16 {%0,%1,%2,%3}, [%4];"
                 : "=r"(r[0]), "=r"(r[1]), "=r"(r[2]), "=r"(r[3]) : "r"(addr));
}
DEVFN void mma_f16(float* d, const uint32_t* a, uint32_t b0, uint32_t b1) {
    asm volatile(
        "mma.sync.aligned.m16n8k16.row.col.f32.f16.f16.f32 "
        "{%0,%1,%2,%3}, {%4,%5,%6,%7}, {%8,%9}, {%0,%1,%2,%3};"
        : "+f"(d[0]), "+f"(d[1]), "+f"(d[2]), "+f"(d[3])
        : "r"(a[0]), "r"(a[1]), "r"(a[2]), "r"(a[3]), "r"(b0), "r"(b1));
}
DEVFN void cp_async16(uint32_t smem_dst, const void* gsrc) {
    asm volatile("cp.async.cg.shared.global [%0], [%1], 16;"
                 :: "r"(smem_dst), "l"(gsrc) : "memory");
}
#define CP_COMMIT() asm volatile("cp.async.commit_group;" ::: "memory")

// ------------------------- globals -------------------------
__device__ float g_sum[64];
__device__ float g_sumsq[64];
__device__ __align__(16) float g_scale[64];
__device__ __align__(16) float g_shift[64];
// B fragments (fp16): [27][ntile 8][kstep 2][lane 32] x uint2  (4 KB per k)
__device__ __align__(16) uint2 g_Bfrag[27 * 512];
// fp16 data image: row = 32 half = 64B
static const int ROW_CAP = 301056;
__device__ __align__(16) uint8_t g_dataF16[(size_t)ROW_CAP * 64];
__device__ __align__(16) uint8_t g_zero_row[64];   // stays zero

__global__ void zero_stats_kernel() {
    int t = threadIdx.x;
    if (t < 64) { g_sum[t] = 0.0f; g_sumsq[t] = 0.0f; }
}

// ------------------------- data prep: f32 row -> fp16 row -------------------------
__global__ __launch_bounds__(256) void prep_data_kernel(const float* __restrict__ data, int N) {
    int r = blockIdx.x * 256 + threadIdx.x;
    if (r >= N || r >= ROW_CAP) return;
    const float4* src = (const float4*)(data + (size_t)r * 32);
    uint32_t u[16];
    #pragma unroll
    for (int i = 0; i < 8; i++) {
        float4 v = src[i];
        u[2 * i]     = pack_h2(v.x, v.y);
        u[2 * i + 1] = pack_h2(v.z, v.w);
    }
    uint4* dst = (uint4*)(g_dataF16 + (size_t)r * 64);
    #pragma unroll
    for (int i = 0; i < 4; i++)
        dst[i] = make_uint4(u[4 * i], u[4 * i + 1], u[4 * i + 2], u[4 * i + 3]);
}

// ------------------------- weight prep -------------------------
// m16n8k16 B frag: lane l: reg0 = B[2q+{0,1}][g], reg1 = B[2q+8+{0,1}][g],
// q=l&3, g=l>>2. kstep 0 = channels 0:16, kstep 1 = 16:32.
__global__ __launch_bounds__(256) void prep_weights_kernel(const float* __restrict__ weight) {
    int k = blockIdx.x;
    int lane = threadIdx.x & 31;
    int nt = threadIdx.x >> 5;
    int q = lane & 3;
    int g = lane >> 2;
    int n = nt * 8 + g;
    const float* wk = weight + k * 2048;  // [32 c][64 o]

    #pragma unroll
    for (int ks = 0; ks < 2; ks++) {
        int cb = ks * 16 + 2 * q;
        uint2 v;
        v.x = pack_h2(wk[cb * 64 + n],       wk[(cb + 1) * 64 + n]);
        v.y = pack_h2(wk[(cb + 8) * 64 + n], wk[(cb + 9) * 64 + n]);
        g_Bfrag[((k * 8 + nt) * 2 + ks) * 32 + lane] = v;
    }
}

// ------------------------- conv kernel -------------------------
// dynamic smem: A 3x8KB | B 3x4KB = 36 KB (plus ~18KB static -> needs opt-in)
__global__ __launch_bounds__(256) void conv_kernel(
    const int* __restrict__ neigh,      // [N,27] int32
    float* __restrict__ out,            // [N,64]
    int N)
{
    extern __shared__ __align__(256) uint8_t dyn[];
    const uint32_t aA = smem_u32(dyn);
    const uint32_t aB = aA + 3 * 8192;
    uint8_t* sB = dyn + 3 * 8192;
    __shared__ int s_idx[27 * 128];
    __shared__ float red_sum[8 * 64];
    __shared__ float red_sq[8 * 64];

    const int tid = threadIdx.x;
    const int w = tid >> 5;
    const int lane = tid & 31;
    const int n0 = blockIdx.x * 128;

    // preload neighbor indices (coalesced)
    {
        const int* base = neigh + (size_t)n0 * 27;
        for (int e = tid; e < 27 * 128; e += 256) {
            int r = e / 27;
            int kk = e - r * 27;
            int v = (n0 + r < N) ? base[e] : -1;
            if ((unsigned)v >= (unsigned)N) v = -1;
            s_idx[kk * 128 + r] = v;
        }
    }
    __syncthreads();

    // A gather mapping: thread -> row (tid>>1), chunks j0 = (tid&1)*2, j0+1
    const int grow = tid >> 1;
    const int j0 = (tid & 1) * 2;
    const uint32_t gsw = ((uint32_t)(grow >> 1) & 3);     // chunk xor for this row
    const uint32_t adst_base = (uint32_t)grow * 64;

    // ldmatrix relative offsets (ks = 0,1), conflict-free chunk swizzle
    uint32_t lm_rel[2];
    {
        int row = w * 16 + (lane & 15);
        uint32_t rx = ((uint32_t)(row >> 1) & 3);
        #pragma unroll
        for (int ks = 0; ks < 2; ks++) {
            uint32_t chunk = (uint32_t)(ks * 2 + (lane >> 4));
            lm_rel[ks] = (uint32_t)row * 64 + ((chunk ^ rx) << 4);
        }
    }

    float acc[8][4];
    #pragma unroll
    for (int nt = 0; nt < 8; nt++)
        #pragma unroll
        for (int i = 0; i < 4; i++) acc[nt][i] = 0.0f;

    auto issue_stage = [&](int k, int s) {
        // B frags: 4KB contiguous, 1 chunk/thread
        cp_async16(aB + s * 4096 + tid * 16,
                   (const uint8_t*)g_Bfrag + (size_t)k * 4096 + tid * 16);
        // A gather: 2 chunks (32B of one row)
        int idx = s_idx[k * 128 + grow];
        const uint8_t* src = (idx >= 0) ? g_dataF16 + (size_t)idx * 64
                                        : (const uint8_t*)g_zero_row;
        uint32_t db = aA + s * 8192 + adst_base;
        cp_async16(db + (((uint32_t)j0 ^ gsw) << 4),       src + j0 * 16);
        cp_async16(db + ((((uint32_t)j0 + 1) ^ gsw) << 4), src + j0 * 16 + 16);
        CP_COMMIT();
    };

    issue_stage(0, 0);
    issue_stage(1, 1);

    int s = 0;                 // stage of current k
    int s2 = 2;                // stage to fill next
    for (int k = 0; k < 27; k++) {
        if (k < 25) {
            issue_stage(k + 2, s2);
            asm volatile("cp.async.wait_group 2;" ::: "memory");
        } else if (k == 25) {
            asm volatile("cp.async.wait_group 1;" ::: "memory");
        } else {
            asm volatile("cp.async.wait_group 0;" ::: "memory");
        }
        __syncthreads();

        const uint32_t abase = aA + s * 8192;
        uint32_t af[2][4];
        ldmatrix_x4(af[0], abase + lm_rel[0]);
        ldmatrix_x4(af[1], abase + lm_rel[1]);

        const uint2* bbuf = (const uint2*)(sB + s * 4096);
        #pragma unroll
        for (int nt = 0; nt < 8; nt++) {
            const uint2* bp = bbuf + nt * 64 + lane;
            uint2 b0 = bp[0];        // c 0:16
            uint2 b1 = bp[32];       // c 16:32
            mma_f16(acc[nt], af[0], b0.x, b0.y);
            mma_f16(acc[nt], af[1], b1.x, b1.y);
        }
        __syncthreads();   // all readers done before this stage is refilled

        s = (s == 2) ? 0 : s + 1;
        s2 = (s2 == 2) ? 0 : s2 + 1;
    }

    // ---- epilogue ----
    const int q = lane & 3;
    const int g = lane >> 2;
    const int row0 = n0 + w * 16 + g;
    const int row1 = row0 + 8;

    if (row0 < N) {
        float* po = out + (size_t)row0 * 64 + 2 * q;
        #pragma unroll
        for (int nt = 0; nt < 8; nt++)
            *(float2*)(po + nt * 8) = make_float2(acc[nt][0], acc[nt][1]);
    }
    if (row1 < N) {
        float* po = out + (size_t)row1 * 64 + 2 * q;
        #pragma unroll
        for (int nt = 0; nt < 8; nt++)
            *(float2*)(po + nt * 8) = make_float2(acc[nt][2], acc[nt][3]);
    }

    // BN partials (invalid rows contributed exact zeros)
    float ps[16], pq[16];
    #pragma unroll
    for (int nt = 0; nt < 8; nt++) {
        ps[2 * nt]     = acc[nt][0] + acc[nt][2];
        ps[2 * nt + 1] = acc[nt][1] + acc[nt][3];
        pq[2 * nt]     = acc[nt][0] * acc[nt][0] + acc[nt][2] * acc[nt][2];
        pq[2 * nt + 1] = acc[nt][1] * acc[nt][1] + acc[nt][3] * acc[nt][3];
    }
    #pragma unroll
    for (int i = 0; i < 16; i++) {
        #pragma unroll
        for (int off = 4; off < 32; off <<= 1) {
            ps[i] += __shfl_xor_sync(0xffffffffu, ps[i], off);
            pq[i] += __shfl_xor_sync(0xffffffffu, pq[i], off);
        }
    }
    if (g == 0) {
        #pragma unroll
        for (int nt = 0; nt < 8; nt++) {
            int c = nt * 8 + 2 * q;
            red_sum[w * 64 + c]     = ps[2 * nt];
            red_sum[w * 64 + c + 1] = ps[2 * nt + 1];
            red_sq[w * 64 + c]      = pq[2 * nt];
            red_sq[w * 64 + c + 1]  = pq[2 * nt + 1];
        }
    }
    __syncthreads();
    if (tid < 64) {
        float t = 0.f;
        #pragma unroll
        for (int ww = 0; ww < 8; ww++) t += red_sum[ww * 64 + tid];
        atomicAdd(&g_sum[tid], t);
    } else if (tid < 128) {
        int c = tid - 64;
        float t = 0.f;
        #pragma unroll
        for (int ww = 0; ww < 8; ww++) t += red_sq[ww * 64 + c];
        atomicAdd(&g_sumsq[c], t);
    }
}

// ------------------------- BN tail -------------------------
__global__ void finalize_stats_kernel(const float* __restrict__ gamma,
                                      const float* __restrict__ beta,
                                      float invN)
{
    int c = threadIdx.x;
    if (c < 64) {
        float mean = g_sum[c] * invN;
        float var  = fmaxf(g_sumsq[c] * invN - mean * mean, 0.0f);
        float sc   = gamma[c] * rsqrtf(var + 1e-5f);
        g_scale[c] = sc;
        g_shift[c] = beta[c] - mean * sc;
    }
}

__global__ __launch_bounds__(256) void bn_relu_kernel(float* __restrict__ out, int total4) {
    int i = blockIdx.x * 256 + threadIdx.x;
    if (i < total4) {
        float4 x = ((const float4*)out)[i];
        int cq = i & 15;
        float4 sc = ((const float4*)g_scale)[cq];
        float4 sh = ((const float4*)g_shift)[cq];
        float4 y;
        y.x = fmaxf(fmaf(x.x, sc.x, sh.x), 0.0f);
        y.y = fmaxf(fmaf(x.y, sc.y, sh.y), 0.0f);
        y.z = fmaxf(fmaf(x.z, sc.z, sh.z), 0.0f);
        y.w = fmaxf(fmaf(x.w, sc.w, sh.w), 0.0f);
        ((float4*)out)[i] = y;
    }
}

// ------------------------- launch -------------------------
extern "C" void kernel_launch(void* const* d_in, const int* in_sizes, int n_in,
                              void* d_out, int out_size)
{
    const float* data   = (const float*)d_in[0];   // [N,32]
    const int*   neigh  = (const int*)d_in[1];     // [N,27] int32
    const float* weight = (const float*)d_in[2];   // [27,32,64]
    const float* gamma  = (const float*)d_in[3];
    const float* beta   = (const float*)d_in[4];
    float* out = (float*)d_out;

    int N = in_sizes[0] / 32;

    // One-time opt-in: static (~18KB) + dynamic (36KB) exceeds the 48KB default.
    // Runs on the (uncaptured) correctness call; skipped during graph capture.
    static bool configured = false;
    if (!configured) {
        cudaFuncSetAttribute(conv_kernel,
                             cudaFuncAttributeMaxDynamicSharedMemorySize, 36864);
        configured = true;
    }

    zero_stats_kernel<<<1, 64>>>();
    prep_data_kernel<<<(N + 255) / 256, 256>>>(data, N);
    prep_weights_kernel<<<27, 256>>>(weight);
    conv_kernel<<<(N + 127) / 128, 256, 36864>>>(neigh, out, N);
    finalize_stats_kernel<<<1, 64>>>(gamma, beta, 1.0f / (float)N);
    int total4 = N * 16;
    bn_relu_kernel<<<(total4 + 255) / 256, 256>>>(out, total4);
}